// round 1
// baseline (speedup 1.0000x reference)
#include <cuda_runtime.h>
#include <cuda_bf16.h>
#include <cstdint>

// Problem dimensions (fixed by setup_inputs)
#define NQ 4096
#define NK 8192
#define DIM 1024

// ---------------------------------------------------------------------------
// Scratch (device globals -- no allocation in kernel_launch, per harness rules)
// ---------------------------------------------------------------------------
__device__ float g_P[(size_t)NQ * NK];   // exp(score), 128 MB
__device__ float g_qninv[NQ];            // 1/|q|
__device__ float g_kninv[NK];            // 1/|k|
__device__ float g_rsum[NQ];             // softmax denominators

// ---------------------------------------------------------------------------
// Row inverse-norm: one warp per row, 8 rows per 256-thread block.
// ---------------------------------------------------------------------------
__global__ void rownorm_inv_kernel(const float* __restrict__ X,
                                   float* __restrict__ out, int nrows) {
    int row  = blockIdx.x * 8 + (threadIdx.x >> 5);
    int lane = threadIdx.x & 31;
    if (row >= nrows) return;
    const float4* xp = (const float4*)(X + (size_t)row * DIM);
    float s = 0.f;
#pragma unroll
    for (int i = 0; i < 8; i++) {
        float4 v = xp[lane + 32 * i];
        s += v.x * v.x + v.y * v.y + v.z * v.z + v.w * v.w;
    }
#pragma unroll
    for (int o = 16; o > 0; o >>= 1) s += __shfl_xor_sync(0xffffffffu, s, o);
    if (lane == 0) out[row] = rsqrtf(s);
}

// ---------------------------------------------------------------------------
// GEMM1: P[m][n] = exp( (Q[m,:] . K[n,:]) * qninv[m] * kninv[n] )
// A = Q [NQ, DIM] row-major, B = K [NK, DIM] row-major (both K-dim contiguous).
// Tile 128x128x16, 256 threads, 8x8 per thread.
// ---------------------------------------------------------------------------
__global__ __launch_bounds__(256) void gemm1_exp_kernel(
    const float* __restrict__ A, const float* __restrict__ B) {
    __shared__ float As[16][132];
    __shared__ float Bs[16][132];

    int tid = threadIdx.x;
    int tx = tid & 15, ty = tid >> 4;
    int m0 = blockIdx.y * 128, n0 = blockIdx.x * 128;

    int lr = tid >> 2;          // 0..63 : tile row for loads
    int lc = (tid & 3) * 4;     // 0,4,8,12 : k-col within 16

    float acc[8][8] = {};

    for (int k0 = 0; k0 < DIM; k0 += 16) {
#pragma unroll
        for (int j = 0; j < 2; j++) {
            int row = lr + j * 64;
            float4 v = *(const float4*)(A + (size_t)(m0 + row) * DIM + k0 + lc);
            As[lc + 0][row] = v.x; As[lc + 1][row] = v.y;
            As[lc + 2][row] = v.z; As[lc + 3][row] = v.w;
            float4 w = *(const float4*)(B + (size_t)(n0 + row) * DIM + k0 + lc);
            Bs[lc + 0][row] = w.x; Bs[lc + 1][row] = w.y;
            Bs[lc + 2][row] = w.z; Bs[lc + 3][row] = w.w;
        }
        __syncthreads();
#pragma unroll
        for (int kk = 0; kk < 16; kk++) {
            float a[8], b[8];
            *(float4*)&a[0] = *(const float4*)&As[kk][ty * 8];
            *(float4*)&a[4] = *(const float4*)&As[kk][ty * 8 + 4];
            *(float4*)&b[0] = *(const float4*)&Bs[kk][tx * 8];
            *(float4*)&b[4] = *(const float4*)&Bs[kk][tx * 8 + 4];
#pragma unroll
            for (int i = 0; i < 8; i++)
#pragma unroll
                for (int j = 0; j < 8; j++) acc[i][j] += a[i] * b[j];
        }
        __syncthreads();
    }

    // Epilogue: cosine scale + exp, store P.
    float qinv[8], kinv[8];
#pragma unroll
    for (int i = 0; i < 8; i++) qinv[i] = g_qninv[m0 + ty * 8 + i];
#pragma unroll
    for (int j = 0; j < 8; j++) kinv[j] = g_kninv[n0 + tx * 8 + j];

#pragma unroll
    for (int i = 0; i < 8; i++) {
        int m = m0 + ty * 8 + i;
        float p[8];
#pragma unroll
        for (int j = 0; j < 8; j++)
            p[j] = __expf(acc[i][j] * qinv[i] * kinv[j]);
        float* dst = g_P + (size_t)m * NK + n0 + tx * 8;
        *(float4*)(dst)     = make_float4(p[0], p[1], p[2], p[3]);
        *(float4*)(dst + 4) = make_float4(p[4], p[5], p[6], p[7]);
    }
}

// ---------------------------------------------------------------------------
// Row sums of P (softmax denominators). Deterministic (no float atomics).
// ---------------------------------------------------------------------------
__global__ __launch_bounds__(256) void rowsum_kernel() {
    int row = blockIdx.x;
    const float4* p = (const float4*)(g_P + (size_t)row * NK);
    float s = 0.f;
    for (int i = threadIdx.x; i < NK / 4; i += 256) {
        float4 v = p[i];
        s += (v.x + v.y) + (v.z + v.w);
    }
#pragma unroll
    for (int o = 16; o > 0; o >>= 1) s += __shfl_xor_sync(0xffffffffu, s, o);
    __shared__ float red[8];
    if ((threadIdx.x & 31) == 0) red[threadIdx.x >> 5] = s;
    __syncthreads();
    if (threadIdx.x < 8) {
        s = red[threadIdx.x];
        s += __shfl_xor_sync(0x000000ffu, s, 4);
        s += __shfl_xor_sync(0x000000ffu, s, 2);
        s += __shfl_xor_sync(0x000000ffu, s, 1);
        if (threadIdx.x == 0) g_rsum[row] = s;
    }
}

// ---------------------------------------------------------------------------
// GEMM2: C[m][n] = (sum_k P[m][k] * V[k][n]) / rsum[m]
// A = P [NQ, NK] row-major, B = V [NK, DIM] row-major (N-dim contiguous).
// ---------------------------------------------------------------------------
__global__ __launch_bounds__(256) void gemm2_scale_kernel(
    const float* __restrict__ V, float* __restrict__ C) {
    __shared__ float As[16][132];
    __shared__ float Bs[16][132];

    int tid = threadIdx.x;
    int tx = tid & 15, ty = tid >> 4;
    int m0 = blockIdx.y * 128, n0 = blockIdx.x * 128;

    int ar = tid >> 2;          // 0..63
    int ac = (tid & 3) * 4;     // k-col within 16 (A loads, transposed)
    int br = tid >> 5;          // 0..7 (B loads, direct)
    int bc = (tid & 31) * 4;    // n-col within 128

    float acc[8][8] = {};

    for (int k0 = 0; k0 < NK; k0 += 16) {
#pragma unroll
        for (int j = 0; j < 2; j++) {
            int row = ar + j * 64;
            float4 v = *(const float4*)(g_P + (size_t)(m0 + row) * NK + k0 + ac);
            As[ac + 0][row] = v.x; As[ac + 1][row] = v.y;
            As[ac + 2][row] = v.z; As[ac + 3][row] = v.w;
            int brow = br + j * 8;
            float4 w = *(const float4*)(V + (size_t)(k0 + brow) * DIM + n0 + bc);
            *(float4*)&Bs[brow][bc] = w;
        }
        __syncthreads();
#pragma unroll
        for (int kk = 0; kk < 16; kk++) {
            float a[8], b[8];
            *(float4*)&a[0] = *(const float4*)&As[kk][ty * 8];
            *(float4*)&a[4] = *(const float4*)&As[kk][ty * 8 + 4];
            *(float4*)&b[0] = *(const float4*)&Bs[kk][tx * 8];
            *(float4*)&b[4] = *(const float4*)&Bs[kk][tx * 8 + 4];
#pragma unroll
            for (int i = 0; i < 8; i++)
#pragma unroll
                for (int j = 0; j < 8; j++) acc[i][j] += a[i] * b[j];
        }
        __syncthreads();
    }

#pragma unroll
    for (int i = 0; i < 8; i++) {
        int m = m0 + ty * 8 + i;
        float rinv = 1.0f / g_rsum[m];
        float* dst = C + (size_t)m * DIM + n0 + tx * 8;
        *(float4*)(dst) = make_float4(acc[i][0] * rinv, acc[i][1] * rinv,
                                      acc[i][2] * rinv, acc[i][3] * rinv);
        *(float4*)(dst + 4) = make_float4(acc[i][4] * rinv, acc[i][5] * rinv,
                                          acc[i][6] * rinv, acc[i][7] * rinv);
    }
}

// ---------------------------------------------------------------------------
// Launch: norms -> GEMM1(+exp) -> rowsum -> GEMM2(+scale)
// ---------------------------------------------------------------------------
extern "C" void kernel_launch(void* const* d_in, const int* in_sizes, int n_in,
                              void* d_out, int out_size) {
    const float* Q = (const float*)d_in[0];   // [4096, 1024]
    const float* K = (const float*)d_in[1];   // [8192, 1024] (keys == values)
    float* out = (float*)d_out;               // [4096, 1024]
    (void)in_sizes; (void)n_in; (void)out_size;

    float *qninv_p, *kninv_p;
    cudaGetSymbolAddress((void**)&qninv_p, g_qninv);
    cudaGetSymbolAddress((void**)&kninv_p, g_kninv);

    rownorm_inv_kernel<<<NQ / 8, 256>>>(Q, qninv_p, NQ);
    rownorm_inv_kernel<<<NK / 8, 256>>>(K, kninv_p, NK);

    dim3 g1(NK / 128, NQ / 128);   // (64, 32)
    gemm1_exp_kernel<<<g1, 256>>>(Q, K);

    rowsum_kernel<<<NQ, 256>>>();

    dim3 g2(DIM / 128, NQ / 128);  // (8, 32)
    gemm2_scale_kernel<<<g2, 256>>>(K, out);
}

// round 3
// speedup vs baseline: 5.7757x; 5.7757x over previous
#include <cuda_runtime.h>
#include <cuda_fp16.h>
#include <cstdint>

#define NQ 4096
#define NK 8192
#define DIM 1024

// ---------------------------------------------------------------------------
// Scratch (device globals; no allocation in kernel_launch)
// ---------------------------------------------------------------------------
__device__ __half g_Qh[(size_t)NQ * DIM];     //  8 MB fp16 Q
__device__ __half g_Kh[(size_t)NK * DIM];     // 16 MB fp16 K
__device__ __half g_Vt[(size_t)DIM * NK];     // 16 MB fp16 V^T [n][k]
__device__ __half g_R [(size_t)NQ * NK];      // 64 MB fp16 R = exp(cos)-1
__device__ float  g_qninv[NQ];
__device__ float  g_kninv[NK];
__device__ float  g_rsum[NQ];
__device__ float  g_colsum[DIM];
__device__ float  g_colpart[64][DIM];

// ---------------------------------------------------------------------------
// PTX helpers (plain sm_103-compatible: mma.sync / ldmatrix / cp.async only)
// ---------------------------------------------------------------------------
__device__ __forceinline__ uint32_t smem_u32(const void* p) {
    uint32_t a;
    asm("{ .reg .u64 t; cvta.to.shared.u64 t, %1; cvt.u32.u64 %0, t; }"
        : "=r"(a) : "l"(p));
    return a;
}

__device__ __forceinline__ void cp16(uint32_t dst, const void* src) {
    asm volatile("cp.async.cg.shared.global [%0], [%1], 16;" :: "r"(dst), "l"(src));
}
#define CP_COMMIT() asm volatile("cp.async.commit_group;" ::: "memory")
#define CP_WAIT(N)  asm volatile("cp.async.wait_group %0;" :: "n"(N) : "memory")

__device__ __forceinline__ void ldsm_x4(uint32_t (&r)[4], uint32_t addr) {
    asm volatile("ldmatrix.sync.aligned.m8n8.x4.shared.b16 {%0,%1,%2,%3}, [%4];"
        : "=r"(r[0]), "=r"(r[1]), "=r"(r[2]), "=r"(r[3]) : "r"(addr));
}

__device__ __forceinline__ void mma16816(float (&d)[4], const uint32_t (&a)[4],
                                         uint32_t b0, uint32_t b1) {
    asm volatile("mma.sync.aligned.m16n8k16.row.col.f32.f16.f16.f32 "
        "{%0,%1,%2,%3}, {%4,%5,%6,%7}, {%8,%9}, {%0,%1,%2,%3};"
        : "+f"(d[0]), "+f"(d[1]), "+f"(d[2]), "+f"(d[3])
        : "r"(a[0]), "r"(a[1]), "r"(a[2]), "r"(a[3]), "r"(b0), "r"(b1));
}

// ---------------------------------------------------------------------------
// Aux kernels
// ---------------------------------------------------------------------------
__global__ void convert_norm_kernel(const float* __restrict__ X,
                                    __half* __restrict__ Xh,
                                    float* __restrict__ ninv) {
    int row  = blockIdx.x * 8 + (threadIdx.x >> 5);
    int lane = threadIdx.x & 31;
    const float4* xp = (const float4*)(X + (size_t)row * DIM);
    __half2* op = (__half2*)(Xh + (size_t)row * DIM);
    float s = 0.f;
#pragma unroll
    for (int i = 0; i < 8; i++) {
        float4 v = xp[lane + 32 * i];
        s += v.x * v.x + v.y * v.y + v.z * v.z + v.w * v.w;
        op[(lane + 32 * i) * 2]     = __floats2half2_rn(v.x, v.y);
        op[(lane + 32 * i) * 2 + 1] = __floats2half2_rn(v.z, v.w);
    }
#pragma unroll
    for (int o = 16; o > 0; o >>= 1) s += __shfl_xor_sync(0xffffffffu, s, o);
    if (lane == 0) ninv[row] = rsqrtf(s);
}

__global__ void transpose_v_kernel(const float* __restrict__ V) {
    __shared__ float tile[32][33];
    int n0 = blockIdx.x * 32, k0 = blockIdx.y * 32;
    int tx = threadIdx.x, ty = threadIdx.y;           // 32 x 8
#pragma unroll
    for (int i = 0; i < 4; i++)
        tile[ty + 8 * i][tx] = V[(size_t)(k0 + ty + 8 * i) * DIM + n0 + tx];
    __syncthreads();
#pragma unroll
    for (int i = 0; i < 4; i++)
        g_Vt[(size_t)(n0 + ty + 8 * i) * NK + k0 + tx] = __float2half(tile[tx][ty + 8 * i]);
}

__global__ void colsum_part_kernel(const float* __restrict__ V) {
    int n = blockIdx.x * 256 + threadIdx.x;
    int kbase = blockIdx.y * 128;
    float s = 0.f;
    for (int k = 0; k < 128; k++) s += V[(size_t)(kbase + k) * DIM + n];
    g_colpart[blockIdx.y][n] = s;
}

__global__ void colsum_fin_kernel() {
    int n = blockIdx.x * 256 + threadIdx.x;
    float s = 0.f;
#pragma unroll
    for (int j = 0; j < 64; j++) s += g_colpart[j][n];
    g_colsum[n] = s;
}

// rsum[m] = NK + sum_k R[m][k]   (since p = 1 + r)
__global__ void rowsum_kernel() {
    int row  = blockIdx.x * 8 + (threadIdx.x >> 5);
    int lane = threadIdx.x & 31;
    const uint4* rp = (const uint4*)(g_R + (size_t)row * NK);
    float s = 0.f;
#pragma unroll
    for (int i = 0; i < 32; i++) {
        uint4 u = rp[lane + 32 * i];
        const __half2* h = (const __half2*)&u;
#pragma unroll
        for (int j = 0; j < 4; j++) { float2 f = __half22float2(h[j]); s += f.x + f.y; }
    }
#pragma unroll
    for (int o = 16; o > 0; o >>= 1) s += __shfl_xor_sync(0xffffffffu, s, o);
    if (lane == 0) g_rsum[row] = (float)NK + s;
}

// ---------------------------------------------------------------------------
// HMMA fp16 GEMM: D[128 x 128] per CTA, K-chunks of 32, cp.async 3-stage.
//   MODE 0: epilogue r = exp(acc * qninv[m] * kninv[n]) - 1 -> g_R (fp16)
//   MODE 1: epilogue (acc + colsum[n]) / rsum[m] -> Cout (fp32)
// A rows m0.. (K-major, lda), B rows n0.. (K-major, ldb).
// ---------------------------------------------------------------------------
#define BM 128
#define BN 128
#define BK 32
#define STAGES 3
#define APITCH 40                              // halves per row (pad 32->40)
#define ST_A_BYTES (BM * APITCH * 2)           // 10240
#define ST_BYTES   (2 * ST_A_BYTES)            // 20480 (A + B)
#define SMEM_BYTES (STAGES * ST_BYTES)         // 61440

template <int MODE>
__global__ __launch_bounds__(256, 2) void hgemm_kernel(
    const __half* __restrict__ A, const __half* __restrict__ B,
    int lda, int ldb, int kdim, float* __restrict__ Cout) {
    extern __shared__ char smem[];
    const uint32_t sbase = smem_u32(smem);
    const int t = threadIdx.x;
    const int m0 = blockIdx.y * BM, n0 = blockIdx.x * BN;
    const int lane = t & 31, w = t >> 5;
    const int wm = w >> 1, wn = w & 1;          // 4 x 2 warp grid; tile 32m x 64n

    const int lr = t >> 2;                      // 0..63 unused; real: r = idx>>2
    (void)lr;

    auto load_stage = [&](int ci, int st) {
        uint32_t sa = sbase + st * ST_BYTES;
        uint32_t sb = sa + ST_A_BYTES;
        int k0 = ci * BK;
#pragma unroll
        for (int j = 0; j < 2; j++) {
            int idx = t + 256 * j;              // 0..511
            int r = idx >> 2, c = idx & 3;      // 128 rows x 4 chunks(16B)
            cp16(sa + r * (APITCH * 2) + c * 16,
                 A + (size_t)(m0 + r) * lda + k0 + c * 8);
            cp16(sb + r * (APITCH * 2) + c * 16,
                 B + (size_t)(n0 + r) * ldb + k0 + c * 8);
        }
    };

    float acc[2][8][4] = {};

    const int KT = kdim / BK;
    load_stage(0, 0); CP_COMMIT();
    load_stage(1, 1); CP_COMMIT();

    // ldmatrix base offsets for this thread
    const int lrow = lane & 15;                 // row within 16
    const int lcol = (lane >> 4) * 16;          // byte offset: 0 or 16 (8 halves)

    for (int i = 0; i < KT; i++) {
        CP_WAIT(1);
        __syncthreads();
        if (i + 2 < KT) load_stage(i + 2, (i + 2) % STAGES);
        CP_COMMIT();

        uint32_t sa = sbase + (i % STAGES) * ST_BYTES;
        uint32_t sb = sa + ST_A_BYTES;

#pragma unroll
        for (int kk = 0; kk < 2; kk++) {
            uint32_t a[2][4], bf[4][4];
#pragma unroll
            for (int mi = 0; mi < 2; mi++) {
                int row = wm * 32 + mi * 16 + lrow;
                ldsm_x4(a[mi], sa + row * (APITCH * 2) + kk * 32 + lcol);
            }
#pragma unroll
            for (int ni = 0; ni < 4; ni++) {
                int row = wn * 64 + ni * 16 + lrow;
                ldsm_x4(bf[ni], sb + row * (APITCH * 2) + kk * 32 + lcol);
            }
#pragma unroll
            for (int mi = 0; mi < 2; mi++)
#pragma unroll
                for (int ni = 0; ni < 4; ni++) {
                    mma16816(acc[mi][2 * ni],     a[mi], bf[ni][0], bf[ni][2]);
                    mma16816(acc[mi][2 * ni + 1], a[mi], bf[ni][1], bf[ni][3]);
                }
        }
    }

    // ---- Epilogue ----
    const int g = lane >> 2, q = lane & 3;
    const int rbase = m0 + wm * 32;
    const int cbase = n0 + wn * 64;

    if (MODE == 0) {
        float kn[8][2];
#pragma unroll
        for (int nj = 0; nj < 8; nj++) {
            int c = cbase + nj * 8 + q * 2;
            kn[nj][0] = g_kninv[c]; kn[nj][1] = g_kninv[c + 1];
        }
#pragma unroll
        for (int mi = 0; mi < 2; mi++) {
            int r0 = rbase + mi * 16 + g;
            float qi0 = g_qninv[r0], qi1 = g_qninv[r0 + 8];
#pragma unroll
            for (int nj = 0; nj < 8; nj++) {
                int c = cbase + nj * 8 + q * 2;
                __half2 h0 = __floats2half2_rn(
                    __expf(acc[mi][nj][0] * qi0 * kn[nj][0]) - 1.f,
                    __expf(acc[mi][nj][1] * qi0 * kn[nj][1]) - 1.f);
                __half2 h1 = __floats2half2_rn(
                    __expf(acc[mi][nj][2] * qi1 * kn[nj][0]) - 1.f,
                    __expf(acc[mi][nj][3] * qi1 * kn[nj][1]) - 1.f);
                *(__half2*)(g_R + (size_t)r0 * NK + c) = h0;
                *(__half2*)(g_R + (size_t)(r0 + 8) * NK + c) = h1;
            }
        }
    } else {
        float cs[8][2];
#pragma unroll
        for (int nj = 0; nj < 8; nj++) {
            int c = cbase + nj * 8 + q * 2;
            cs[nj][0] = g_colsum[c]; cs[nj][1] = g_colsum[c + 1];
        }
#pragma unroll
        for (int mi = 0; mi < 2; mi++) {
            int r0 = rbase + mi * 16 + g;
            float ri0 = 1.0f / g_rsum[r0], ri1 = 1.0f / g_rsum[r0 + 8];
#pragma unroll
            for (int nj = 0; nj < 8; nj++) {
                int c = cbase + nj * 8 + q * 2;
                float2 o0 = make_float2((acc[mi][nj][0] + cs[nj][0]) * ri0,
                                        (acc[mi][nj][1] + cs[nj][1]) * ri0);
                float2 o1 = make_float2((acc[mi][nj][2] + cs[nj][0]) * ri1,
                                        (acc[mi][nj][3] + cs[nj][1]) * ri1);
                *(float2*)(Cout + (size_t)r0 * DIM + c) = o0;
                *(float2*)(Cout + (size_t)(r0 + 8) * DIM + c) = o1;
            }
        }
    }
}

// ---------------------------------------------------------------------------
// Launch
// ---------------------------------------------------------------------------
extern "C" void kernel_launch(void* const* d_in, const int* in_sizes, int n_in,
                              void* d_out, int out_size) {
    const float* Q = (const float*)d_in[0];   // [4096, 1024]
    const float* K = (const float*)d_in[1];   // [8192, 1024] (keys == values)
    float* out = (float*)d_out;               // [4096, 1024]
    (void)in_sizes; (void)n_in; (void)out_size;

    void *Qh, *Kh, *R, *qn, *kn;
    cudaGetSymbolAddress(&Qh, g_Qh);
    cudaGetSymbolAddress(&Kh, g_Kh);
    cudaGetSymbolAddress(&R,  g_R);
    cudaGetSymbolAddress(&qn, g_qninv);
    cudaGetSymbolAddress(&kn, g_kninv);
    void* Vt; cudaGetSymbolAddress(&Vt, g_Vt);

    cudaFuncSetAttribute(hgemm_kernel<0>, cudaFuncAttributeMaxDynamicSharedMemorySize, SMEM_BYTES);
    cudaFuncSetAttribute(hgemm_kernel<1>, cudaFuncAttributeMaxDynamicSharedMemorySize, SMEM_BYTES);

    convert_norm_kernel<<<NQ / 8, 256>>>(Q, (__half*)Qh, (float*)qn);
    convert_norm_kernel<<<NK / 8, 256>>>(K, (__half*)Kh, (float*)kn);
    transpose_v_kernel<<<dim3(DIM / 32, NK / 32), dim3(32, 8)>>>(K);
    colsum_part_kernel<<<dim3(DIM / 256, 64), 256>>>(K);
    colsum_fin_kernel<<<DIM / 256, 256>>>();

    // GEMM1: R = exp(cos(Q,K)) - 1   [4096 x 8192]
    hgemm_kernel<0><<<dim3(NK / BN, NQ / BM), 256, SMEM_BYTES>>>(
        (const __half*)Qh, (const __half*)Kh, DIM, DIM, DIM, nullptr);

    rowsum_kernel<<<NQ / 8, 256>>>();

    // GEMM2: out = (R . V + colsumV) / rsum   [4096 x 1024]
    hgemm_kernel<1><<<dim3(DIM / BN, NQ / BM), 256, SMEM_BYTES>>>(
        (const __half*)R, (const __half*)Vt, NK, NK, NK, out);
}